// round 12
// baseline (speedup 1.0000x reference)
#include <cuda_runtime.h>
#include <cuda_fp16.h>
#include <cstdint>

// EFLSTM, fp16 mma.sync, persistent recurrence kernel.
//   phase 1: xg = x @ Wih^T + bias  (parallel fp16 GEMM, fp32 out, 1GB scratch)
//   phase 2: ONE persistent kernel, 128 co-resident CTAs, loops t=0..255 with a
//            grid-wide atomic barrier per step. W_hh tile (128KB) resident in smem;
//            h streamed via 4-stage cp.async.bulk ring with continuous phase counter.
//   phase 3: MLP head
// Packed gmem layouts chunk-major, PRE-SWIZZLED (exact smem image).
// Gate cols permuted n = j*4 + band so the cell update is CTA-local.

#define BB 256
#define TT 256
#define D_TXT 300
#define D_AUD 74
#define D_VIS 35
#define DD 409
#define HH 1024
#define G4 4096
#define XP 448
#define NCELL 512

// ---------------- device scratch ----------------
__device__ __half g_hp[2][16 * 256 * 64];            // h images [buf], fp16
__device__ float g_c[BB * HH];
__device__ float g_hf[BB * HH];
__device__ __half g_wpk[(size_t)16 * G4 * 64];       // Whh image
__device__ __half g_wipk[(size_t)7 * G4 * 64];       // Wih image
__device__ __half g_xpk[(size_t)TT * 7 * BB * 64];   // x image
__device__ float g_bsum[G4];
__device__ float g_xg[(size_t)TT * BB * G4];
__device__ int g_ctr;                                // grid barrier counter

// ---------------- helpers ----------------
__device__ __forceinline__ uint32_t s2u(const void* p) {
    uint32_t a;
    asm("{ .reg .u64 t; cvta.to.shared.u64 t, %1; cvt.u32.u64 %0, t; }" : "=r"(a) : "l"(p));
    return a;
}
#define MBINIT(a, c) asm volatile("mbarrier.init.shared.b64 [%0], %1;" ::"r"(a), "r"(c) : "memory")
#define MBARRIVE(a) asm volatile("mbarrier.arrive.shared.b64 _, [%0];" ::"r"(a) : "memory")
#define MBWAIT(a, ph) do {                                                                  \
    uint32_t _d;                                                                            \
    asm volatile("{\n .reg .pred p;\n mbarrier.try_wait.parity.acquire.cta.shared::cta.b64 p,[%1],%2;\n selp.b32 %0,1,0,p;\n}" \
                 : "=r"(_d) : "r"(a), "r"(ph) : "memory");                                  \
    while (!_d) {                                                                           \
        asm volatile("{\n .reg .pred p;\n mbarrier.try_wait.parity.acquire.cta.shared::cta.b64 p,[%1],%2,0x989680;\n selp.b32 %0,1,0,p;\n}" \
                     : "=r"(_d) : "r"(a), "r"(ph) : "memory");                              \
    }                                                                                       \
} while (0)
#define MBEXPECT(bar, bytes) \
    asm volatile("mbarrier.arrive.expect_tx.shared.b64 _, [%0], %1;" ::"r"(bar), "r"(bytes) : "memory")
#define BULK(dst, src, bytes, bar)                                                          \
    asm volatile("cp.async.bulk.shared::cluster.global.mbarrier::complete_tx::bytes "       \
                 "[%0], [%1], %2, [%3];"                                                    \
                 ::"r"(dst), "l"((const void*)(src)), "r"(bytes), "r"(bar) : "memory")
#define BARC() asm volatile("bar.sync 1, 256;" ::: "memory")
#define LDSM4(r, a)                                                                         \
    asm volatile("ldmatrix.sync.aligned.m8n8.x4.shared.b16 {%0,%1,%2,%3}, [%4];"            \
                 : "=r"((r)[0]), "=r"((r)[1]), "=r"((r)[2]), "=r"((r)[3]) : "r"(a))
#define MMAH(acc, a, b0, b1)                                                                \
    asm volatile("mma.sync.aligned.m16n8k16.row.col.f32.f16.f16.f32 "                       \
                 "{%0,%1,%2,%3}, {%4,%5,%6,%7}, {%8,%9}, {%0,%1,%2,%3};"                    \
                 : "+f"((acc)[0]), "+f"((acc)[1]), "+f"((acc)[2]), "+f"((acc)[3])           \
                 : "r"((a)[0]), "r"((a)[1]), "r"((a)[2]), "r"((a)[3]), "r"(b0), "r"(b1))

// single-term fp16 chunk over K=64. Warp tile (TM*16) x 32.
// smem tiles: row-major [rows][64 fp16], 128B/row, swizzle off ^ ((row&7)<<4).
template <int TM>
__device__ __forceinline__ void fused1_chunk(
    uint32_t sA, uint32_t sB, int mbase, int nbase, int lane, float acc[TM][4][4])
{
#pragma unroll
    for (int kk = 0; kk < 4; kk++) {
        uint32_t b[2][4];
#pragma unroll
        for (int tn = 0; tn < 2; tn++) {
            const uint32_t g = (uint32_t)(lane >> 3);
            const uint32_t row = (uint32_t)(nbase + tn * 16) + ((g >> 1) << 3) + (uint32_t)(lane & 7);
            const uint32_t kb = (uint32_t)(kk * 32) + ((g & 1u) << 4);
            const uint32_t off = row * 128u + (kb ^ ((row & 7u) << 4));
            LDSM4(b[tn], sB + off);
        }
#pragma unroll
        for (int tm = 0; tm < TM; tm++) {
            uint32_t a[4];
            const uint32_t row = (uint32_t)(mbase + tm * 16 + (lane & 15));
            const uint32_t kb = (uint32_t)(kk * 32) + ((uint32_t)(lane >> 4) << 4);
            const uint32_t off = row * 128u + (kb ^ ((row & 7u) << 4));
            LDSM4(a, sA + off);
#pragma unroll
            for (int tn = 0; tn < 4; tn++)
                MMAH(acc[tm][tn], a, b[tn >> 1][(tn & 1) * 2], b[tn >> 1][(tn & 1) * 2 + 1]);
        }
    }
}

template <int TM>
__device__ __forceinline__ void store_acc(float* sacc, int pitch, float acc[TM][4][4],
                                          int mbase, int nbase, int lane) {
#pragma unroll
    for (int tm = 0; tm < TM; tm++)
#pragma unroll
        for (int tn = 0; tn < 4; tn++) {
            const int r = mbase + tm * 16 + (lane >> 2);
            const int cc = nbase + tn * 8 + (lane & 3) * 2;
            *(float2*)&sacc[r * pitch + cc] = make_float2(acc[tm][tn][0], acc[tm][tn][1]);
            *(float2*)&sacc[(r + 8) * pitch + cc] = make_float2(acc[tm][tn][2], acc[tm][tn][3]);
        }
}

// ---------------- prep kernels (pre-swizzled chunk-major fp16 images) ----------------
__global__ void init_kernel() {
    int i = blockIdx.x * blockDim.x + threadIdx.x;
    if (i < BB * HH) {
        g_hp[0][i] = __float2half(0.f);
        g_c[i] = 0.f;
    }
    if (i == 0) g_ctr = 0;
}

__global__ void prep_w(const float* __restrict__ Whh) {
    size_t i = (size_t)blockIdx.x * 256 + threadIdx.x;
    if (i >= (size_t)G4 * HH) return;
    int n = (int)(i / HH), k = (int)(i % HH);
    int gc = (n & 3) * HH + (n >> 2);
    float w = Whh[(size_t)gc * HH + k];
    int ck = k >> 6, col = k & 63;
    int unit = (col >> 3) ^ (n & 7);
    g_wpk[((size_t)ck * G4 + n) * 64 + unit * 8 + (col & 7)] = __float2half_rn(w);
}

__global__ void prep_wi(const float* __restrict__ Wih, const float* __restrict__ bih,
                        const float* __restrict__ bhh) {
    size_t i = (size_t)blockIdx.x * 256 + threadIdx.x;
    if (i >= (size_t)G4 * XP) return;
    int n = (int)(i / XP), k = (int)(i % XP);
    int gc = (n & 3) * HH + (n >> 2);
    float w = (k < DD) ? Wih[(size_t)gc * DD + k] : 0.f;
    int ck = k >> 6, col = k & 63;
    int unit = (col >> 3) ^ (n & 7);
    g_wipk[((size_t)ck * G4 + n) * 64 + unit * 8 + (col & 7)] = __float2half_rn(w);
    if (k == 0) g_bsum[n] = bih[gc] + bhh[gc];
}

__global__ void prep_x(const float* __restrict__ xt, const float* __restrict__ xa,
                       const float* __restrict__ xv) {
    size_t i = (size_t)blockIdx.x * 256 + threadIdx.x;
    if (i >= (size_t)TT * BB * XP) return;
    int d = (int)(i % XP);
    size_t tb = i / XP;
    int b = (int)(tb % BB), t = (int)(tb / BB);
    float v = 0.f;
    if (d < D_TXT)              v = xt[((size_t)b * TT + t) * D_TXT + d];
    else if (d < D_TXT + D_AUD) v = xa[((size_t)b * TT + t) * D_AUD + (d - D_TXT)];
    else if (d < DD)            v = xv[((size_t)b * TT + t) * D_VIS + (d - D_TXT - D_AUD)];
    int ck = d >> 6, col = d & 63;
    int unit = (col >> 3) ^ (b & 7);
    g_xpk[(((size_t)t * 7 + ck) * BB + b) * 64 + unit * 8 + (col & 7)] = __float2half_rn(v);
}

// ---------------- xg GEMM: xg = x @ Wih^T + bias (fp16, 1 term) ----------------
// 128x128 tiles, grid (32, 512). 7 chunks, 4 stages x 32KB (A|B).
#define XG_PITCH 132
#define XG_STAGE 32768u
__global__ __launch_bounds__(288, 1) void xg_kernel() {
    extern __shared__ __align__(128) char dsm[];
    __shared__ __align__(8) uint64_t s_full[4], s_empty[4];
    const int tid = threadIdx.x;
    const int lane = tid & 31, wid = tid >> 5;
    const int r0 = blockIdx.y * 128, n0 = blockIdx.x * 128;
    const int t = blockIdx.y >> 1, b0 = (blockIdx.y & 1) * 128;
    const uint32_t sb = s2u(dsm);
    const uint32_t fmb = s2u(s_full), emb = s2u(s_empty);

    if (tid == 0)
        for (int s = 0; s < 4; s++) { MBINIT(fmb + s * 8, 1); MBINIT(emb + s * 8, 256); }
    __syncthreads();

    if (tid >= 256) {
        if (tid == 256) {
            for (int ck = 0; ck < 7; ck++) {
                const int s = ck & 3;
                if (ck >= 4) MBWAIT(emb + s * 8, ((ck >> 2) - 1) & 1);
                const uint32_t st = sb + (uint32_t)s * XG_STAGE;
                const uint32_t bar = fmb + s * 8;
                MBEXPECT(bar, 32768u);
                BULK(st,          &g_xpk[(((size_t)t * 7 + ck) * BB + b0) * 64], 16384u, bar);
                BULK(st + 16384u, &g_wipk[((size_t)ck * G4 + n0) * 64],          16384u, bar);
            }
        }
        return;
    }

    const int wy = wid >> 2, wx = wid & 3;
    float acc[4][4][4];
#pragma unroll
    for (int i = 0; i < 4; i++)
#pragma unroll
        for (int j = 0; j < 4; j++)
#pragma unroll
            for (int k = 0; k < 4; k++) acc[i][j][k] = 0.f;

#pragma unroll 1
    for (int ck = 0; ck < 7; ck++) {
        const int s = ck & 3;
        MBWAIT(fmb + s * 8, (ck >> 2) & 1);
        const uint32_t st = sb + (uint32_t)s * XG_STAGE;
        fused1_chunk<4>(st, st + 16384u, wy * 64, wx * 32, lane, acc);
        MBARRIVE(emb + s * 8);
    }

    BARC();
    float* sacc = (float*)dsm;
    store_acc<4>(sacc, XG_PITCH, acc, wy * 64, wx * 32, lane);
    BARC();
    for (int e = tid; e < 128 * 32; e += 256) {
        const int m = e >> 5, q = e & 31;
        float4 g = *(float4*)&sacc[m * XG_PITCH + q * 4];
        const float4 bs = *(const float4*)&g_bsum[n0 + q * 4];
        g.x += bs.x; g.y += bs.y; g.z += bs.z; g.w += bs.w;
        *(float4*)&g_xg[(size_t)(r0 + m) * G4 + n0 + q * 4] = g;
    }
}

// ---------------- persistent LSTM recurrence ----------------
// grid (64, 2) = 128 CTAs, 1 per SM, all co-resident. Loops t=0..255 internally.
// smem: W resident [16 chunks x 8KB = 128KB] | A ring [4 stages x 16KB = 64KB].
// Epilogue staging (34816B) aliases the A ring (producer is gated by grid barrier).
#define ST_PITCH 68
#define W_SMEM 131072u
__global__ __launch_bounds__(288, 1) void step_persist() {
    extern __shared__ __align__(128) char dsm[];
    __shared__ __align__(8) uint64_t s_full[4], s_empty[4], s_wbar;
    const int tid = threadIdx.x;
    const int lane = tid & 31, wid = tid >> 5;
    const int m0 = blockIdx.y * 128, n0 = blockIdx.x * 64;
    const uint32_t sb = s2u(dsm);
    const uint32_t amem = sb + W_SMEM;
    const uint32_t fmb = s2u(s_full), emb = s2u(s_empty), wbar = s2u(&s_wbar);
    const int wy = wid >> 1, wx = wid & 1;   // warp grid 4(m) x 2(n), warp tile 32x32

    if (tid == 0) {
        for (int s = 0; s < 4; s++) { MBINIT(fmb + s * 8, 1); MBINIT(emb + s * 8, 256); }
        MBINIT(wbar, 1);
    }
    __syncthreads();

    // load resident W tile once (16 bulks of 8KB)
    if (tid == 256) {
        MBEXPECT(wbar, 131072u);
        for (int ck = 0; ck < 16; ck++)
            BULK(sb + (uint32_t)ck * 8192u, &g_wpk[((size_t)ck * G4 + n0) * 64], 8192u, wbar);
    }
    if (tid < 256) MBWAIT(wbar, 0);

#pragma unroll 1
    for (int t = 0; t < TT; t++) {
        const int rb = t & 1, wb = rb ^ 1;

        if (tid >= 256) {
            if (tid == 256) {
                for (int ck = 0; ck < 16; ck++) {
                    const int it = t * 16 + ck;
                    const int s = it & 3;
                    if (it >= 4) MBWAIT(emb + s * 8, ((it >> 2) - 1) & 1);
                    const uint32_t bar = fmb + s * 8;
                    MBEXPECT(bar, 16384u);
                    BULK(amem + (uint32_t)s * 16384u,
                         &g_hp[rb][((size_t)ck * 256 + m0) * 64], 16384u, bar);
                }
            }
        } else {
            float acc[2][4][4];
#pragma unroll
            for (int i = 0; i < 2; i++)
#pragma unroll
                for (int j = 0; j < 4; j++)
#pragma unroll
                    for (int k = 0; k < 4; k++) acc[i][j][k] = 0.f;

#pragma unroll 1
            for (int ck = 0; ck < 16; ck++) {
                const int it = t * 16 + ck;
                const int s = it & 3;
                MBWAIT(fmb + s * 8, (it >> 2) & 1);
                fused1_chunk<2>(amem + (uint32_t)s * 16384u, sb + (uint32_t)ck * 8192u,
                                wy * 32, wx * 32, lane, acc);
                MBARRIVE(emb + s * 8);
            }

            BARC();
            float* sacc = (float*)(dsm + W_SMEM);   // aliases A ring; producer idle here
            store_acc<2>(sacc, ST_PITCH, acc, wy * 32, wx * 32, lane);
            BARC();

            // cell update: packed n -> j = n>>2, bands i,f,g,o = n&3
            for (int e = tid; e < 128 * 16; e += 256) {
                const int mloc = e >> 4, q = e & 15;
                const int gm = m0 + mloc;
                const float4 g = *(float4*)&sacc[mloc * ST_PITCH + q * 4];
                const float4 xgv = *(const float4*)&g_xg[((size_t)t * BB + gm) * G4 + n0 + q * 4];
                const float gi = g.x + xgv.x;
                const float gf = g.y + xgv.y;
                const float gg = g.z + xgv.z;
                const float go = g.w + xgv.w;
                const float si = 1.f / (1.f + __expf(-gi));
                const float sf = 1.f / (1.f + __expf(-gf));
                const float tg = tanhf(gg);
                const float so = 1.f / (1.f + __expf(-go));
                const int j = (n0 >> 2) + q;
                const size_t cidx = (size_t)gm * HH + j;
                const float c = sf * g_c[cidx] + si * tg;
                g_c[cidx] = c;
                const float h = so * tanhf(c);
                const int ck = j >> 6, col = j & 63;
                const int unit = (col >> 3) ^ (gm & 7);
                g_hp[wb][((size_t)ck * 256 + gm) * 64 + unit * 8 + (col & 7)] = __float2half_rn(h);
                if (t == TT - 1) g_hf[cidx] = h;
            }
            __threadfence();   // publish h before grid barrier
        }

        __syncthreads();       // all 288 threads
        if (tid == 0) {
            atomicAdd(&g_ctr, 1);
            const int target = 128 * (t + 1);
            while (atomicAdd(&g_ctr, 0) < target) { }
            __threadfence();
        }
        __syncthreads();
    }
}

// ---------------- MLP head ----------------
__global__ __launch_bounds__(256) void mlp_kernel(
    const float* __restrict__ W1, const float* __restrict__ b1,
    const float* __restrict__ W2, const float* __restrict__ b2,
    float* __restrict__ out) {
    __shared__ float hrow[HH];
    __shared__ float red[256];
    const int b = blockIdx.x;
    const int tid = threadIdx.x;

    const float* __restrict__ h = &g_hf[(size_t)b * HH];
    for (int k = tid; k < HH; k += 256) hrow[k] = h[k];
    __syncthreads();

    float sum = 0.f;
    for (int cc = tid; cc < NCELL; cc += 256) {
        const float* __restrict__ w = &W1[(size_t)cc * HH];
        float acc = b1[cc];
        for (int k = 0; k < HH; k += 4) {
            const float4 wv = *(const float4*)&w[k];
            acc += hrow[k] * wv.x + hrow[k + 1] * wv.y + hrow[k + 2] * wv.z + hrow[k + 3] * wv.w;
        }
        sum += fmaxf(acc, 0.f) * W2[cc];
    }
    red[tid] = sum;
    __syncthreads();
    for (int s = 128; s > 0; s >>= 1) {
        if (tid < s) red[tid] += red[tid + s];
        __syncthreads();
    }
    if (tid == 0) out[b] = red[0] + b2[0];
}

// ---------------- launch ----------------
extern "C" void kernel_launch(void* const* d_in, const int* in_sizes, int n_in,
                              void* d_out, int out_size) {
    const float* xt  = (const float*)d_in[0];
    const float* xa  = (const float*)d_in[1];
    const float* xv  = (const float*)d_in[2];
    const float* Wih = (const float*)d_in[3];
    const float* Whh = (const float*)d_in[4];
    const float* bih = (const float*)d_in[5];
    const float* bhh = (const float*)d_in[6];
    const float* W1  = (const float*)d_in[7];
    const float* b1  = (const float*)d_in[8];
    const float* W2  = (const float*)d_in[9];
    const float* b2  = (const float*)d_in[10];
    float* out = (float*)d_out;

    const int DSM_XG = 4 * 32768;           // 128KB
    const int DSM_ST = 131072 + 65536;      // 192KB: W resident + A ring
    cudaFuncSetAttribute(xg_kernel, cudaFuncAttributeMaxDynamicSharedMemorySize, DSM_XG);
    cudaFuncSetAttribute(step_persist, cudaFuncAttributeMaxDynamicSharedMemorySize, DSM_ST);

    init_kernel<<<(BB * HH + 255) / 256, 256>>>();
    prep_w<<<(int)(((size_t)G4 * HH + 255) / 256), 256>>>(Whh);
    prep_wi<<<(int)(((size_t)G4 * XP + 255) / 256), 256>>>(Wih, bih, bhh);
    prep_x<<<(int)(((size_t)TT * BB * XP + 255) / 256), 256>>>(xt, xa, xv);
    xg_kernel<<<dim3(32, 512), 288, DSM_XG>>>();
    step_persist<<<dim3(64, 2), 288, DSM_ST>>>();
    mlp_kernel<<<BB, 256>>>(W1, b1, W2, b2, out);
}

// round 13
// speedup vs baseline: 1.5174x; 1.5174x over previous
#include <cuda_runtime.h>
#include <cuda_fp16.h>
#include <cstdint>

// EFLSTM, fp16 mma.sync, persistent recurrence with distributed per-chunk sync.
//   phase 1: xg = x @ Wih^T + bias  (parallel fp16 GEMM, fp32 out, packed [t][nt][m][64])
//   phase 2: ONE persistent kernel, 128 co-resident CTAs, t=0..255. W_hh resident in
//            smem (128KB); h streamed via 3-stage bulk ring; xg prefetched per step;
//            cell state c in REGISTERS; per-chunk atomic progress counters (no grid barrier).
//   phase 3: MLP head
// Gate cols permuted n = j*4 + band. Packed images chunk-major, pre-swizzled.

#define BB 256
#define TT 256
#define D_TXT 300
#define D_AUD 74
#define D_VIS 35
#define DD 409
#define HH 1024
#define G4 4096
#define XP 448
#define NCELL 512

// ---------------- device scratch ----------------
__device__ __half g_hp[2][16 * 256 * 64];            // h images [buf], fp16
__device__ float g_hf[BB * HH];
__device__ __half g_wpk[(size_t)16 * G4 * 64];       // Whh image
__device__ __half g_wipk[(size_t)7 * G4 * 64];       // Wih image
__device__ __half g_xpk[(size_t)TT * 7 * BB * 64];   // x image
__device__ float g_bsum[G4];
__device__ float g_xg[(size_t)TT * 64 * 256 * 64];   // packed [t][nt][m][64]
__device__ int g_ckctr[16];                          // per-chunk progress counters

// ---------------- helpers ----------------
__device__ __forceinline__ uint32_t s2u(const void* p) {
    uint32_t a;
    asm("{ .reg .u64 t; cvta.to.shared.u64 t, %1; cvt.u32.u64 %0, t; }" : "=r"(a) : "l"(p));
    return a;
}
#define MBINIT(a, c) asm volatile("mbarrier.init.shared.b64 [%0], %1;" ::"r"(a), "r"(c) : "memory")
#define MBARRIVE(a) asm volatile("mbarrier.arrive.shared.b64 _, [%0];" ::"r"(a) : "memory")
#define MBWAIT(a, ph) do {                                                                  \
    uint32_t _d;                                                                            \
    asm volatile("{\n .reg .pred p;\n mbarrier.try_wait.parity.acquire.cta.shared::cta.b64 p,[%1],%2;\n selp.b32 %0,1,0,p;\n}" \
                 : "=r"(_d) : "r"(a), "r"(ph) : "memory");                                  \
    while (!_d) {                                                                           \
        asm volatile("{\n .reg .pred p;\n mbarrier.try_wait.parity.acquire.cta.shared::cta.b64 p,[%1],%2,0x989680;\n selp.b32 %0,1,0,p;\n}" \
                     : "=r"(_d) : "r"(a), "r"(ph) : "memory");                              \
    }                                                                                       \
} while (0)
#define MBEXPECT(bar, bytes) \
    asm volatile("mbarrier.arrive.expect_tx.shared.b64 _, [%0], %1;" ::"r"(bar), "r"(bytes) : "memory")
#define BULK(dst, src, bytes, bar)                                                          \
    asm volatile("cp.async.bulk.shared::cluster.global.mbarrier::complete_tx::bytes "       \
                 "[%0], [%1], %2, [%3];"                                                    \
                 ::"r"(dst), "l"((const void*)(src)), "r"(bytes), "r"(bar) : "memory")
#define BARC() asm volatile("bar.sync 1, 256;" ::: "memory")
#define LDSM4(r, a)                                                                         \
    asm volatile("ldmatrix.sync.aligned.m8n8.x4.shared.b16 {%0,%1,%2,%3}, [%4];"            \
                 : "=r"((r)[0]), "=r"((r)[1]), "=r"((r)[2]), "=r"((r)[3]) : "r"(a))
#define MMAH(acc, a, b0, b1)                                                                \
    asm volatile("mma.sync.aligned.m16n8k16.row.col.f32.f16.f16.f32 "                       \
                 "{%0,%1,%2,%3}, {%4,%5,%6,%7}, {%8,%9}, {%0,%1,%2,%3};"                    \
                 : "+f"((acc)[0]), "+f"((acc)[1]), "+f"((acc)[2]), "+f"((acc)[3])           \
                 : "r"((a)[0]), "r"((a)[1]), "r"((a)[2]), "r"((a)[3]), "r"(b0), "r"(b1))

// single-term fp16 chunk over K=64. Warp tile (TM*16) x 32.
// smem tiles: row-major [rows][64 fp16], 128B/row, swizzle off ^ ((row&7)<<4).
template <int TM>
__device__ __forceinline__ void fused1_chunk(
    uint32_t sA, uint32_t sB, int mbase, int nbase, int lane, float acc[TM][4][4])
{
#pragma unroll
    for (int kk = 0; kk < 4; kk++) {
        uint32_t b[2][4];
#pragma unroll
        for (int tn = 0; tn < 2; tn++) {
            const uint32_t g = (uint32_t)(lane >> 3);
            const uint32_t row = (uint32_t)(nbase + tn * 16) + ((g >> 1) << 3) + (uint32_t)(lane & 7);
            const uint32_t kb = (uint32_t)(kk * 32) + ((g & 1u) << 4);
            const uint32_t off = row * 128u + (kb ^ ((row & 7u) << 4));
            LDSM4(b[tn], sB + off);
        }
#pragma unroll
        for (int tm = 0; tm < TM; tm++) {
            uint32_t a[4];
            const uint32_t row = (uint32_t)(mbase + tm * 16 + (lane & 15));
            const uint32_t kb = (uint32_t)(kk * 32) + ((uint32_t)(lane >> 4) << 4);
            const uint32_t off = row * 128u + (kb ^ ((row & 7u) << 4));
            LDSM4(a, sA + off);
#pragma unroll
            for (int tn = 0; tn < 4; tn++)
                MMAH(acc[tm][tn], a, b[tn >> 1][(tn & 1) * 2], b[tn >> 1][(tn & 1) * 2 + 1]);
        }
    }
}

template <int TM>
__device__ __forceinline__ void store_acc(float* sacc, int pitch, float acc[TM][4][4],
                                          int mbase, int nbase, int lane) {
#pragma unroll
    for (int tm = 0; tm < TM; tm++)
#pragma unroll
        for (int tn = 0; tn < 4; tn++) {
            const int r = mbase + tm * 16 + (lane >> 2);
            const int cc = nbase + tn * 8 + (lane & 3) * 2;
            *(float2*)&sacc[r * pitch + cc] = make_float2(acc[tm][tn][0], acc[tm][tn][1]);
            *(float2*)&sacc[(r + 8) * pitch + cc] = make_float2(acc[tm][tn][2], acc[tm][tn][3]);
        }
}

// ---------------- prep kernels (pre-swizzled chunk-major fp16 images) ----------------
__global__ void init_kernel() {
    int i = blockIdx.x * blockDim.x + threadIdx.x;
    if (i < BB * HH) g_hp[0][i] = __float2half(0.f);
    if (i < 16) g_ckctr[i] = 0;
}

__global__ void prep_w(const float* __restrict__ Whh) {
    size_t i = (size_t)blockIdx.x * 256 + threadIdx.x;
    if (i >= (size_t)G4 * HH) return;
    int n = (int)(i / HH), k = (int)(i % HH);
    int gc = (n & 3) * HH + (n >> 2);
    float w = Whh[(size_t)gc * HH + k];
    int ck = k >> 6, col = k & 63;
    int unit = (col >> 3) ^ (n & 7);
    g_wpk[((size_t)ck * G4 + n) * 64 + unit * 8 + (col & 7)] = __float2half_rn(w);
}

__global__ void prep_wi(const float* __restrict__ Wih, const float* __restrict__ bih,
                        const float* __restrict__ bhh) {
    size_t i = (size_t)blockIdx.x * 256 + threadIdx.x;
    if (i >= (size_t)G4 * XP) return;
    int n = (int)(i / XP), k = (int)(i % XP);
    int gc = (n & 3) * HH + (n >> 2);
    float w = (k < DD) ? Wih[(size_t)gc * DD + k] : 0.f;
    int ck = k >> 6, col = k & 63;
    int unit = (col >> 3) ^ (n & 7);
    g_wipk[((size_t)ck * G4 + n) * 64 + unit * 8 + (col & 7)] = __float2half_rn(w);
    if (k == 0) g_bsum[n] = bih[gc] + bhh[gc];
}

__global__ void prep_x(const float* __restrict__ xt, const float* __restrict__ xa,
                       const float* __restrict__ xv) {
    size_t i = (size_t)blockIdx.x * 256 + threadIdx.x;
    if (i >= (size_t)TT * BB * XP) return;
    int d = (int)(i % XP);
    size_t tb = i / XP;
    int b = (int)(tb % BB), t = (int)(tb / BB);
    float v = 0.f;
    if (d < D_TXT)              v = xt[((size_t)b * TT + t) * D_TXT + d];
    else if (d < D_TXT + D_AUD) v = xa[((size_t)b * TT + t) * D_AUD + (d - D_TXT)];
    else if (d < DD)            v = xv[((size_t)b * TT + t) * D_VIS + (d - D_TXT - D_AUD)];
    int ck = d >> 6, col = d & 63;
    int unit = (col >> 3) ^ (b & 7);
    g_xpk[(((size_t)t * 7 + ck) * BB + b) * 64 + unit * 8 + (col & 7)] = __float2half_rn(v);
}

// ---------------- xg GEMM: xg = x @ Wih^T + bias (fp16) -> packed [t][nt][m][64] ----
#define XG_PITCH 132
#define XG_STAGE 32768u
__global__ __launch_bounds__(288, 1) void xg_kernel() {
    extern __shared__ __align__(128) char dsm[];
    __shared__ __align__(8) uint64_t s_full[4], s_empty[4];
    const int tid = threadIdx.x;
    const int lane = tid & 31, wid = tid >> 5;
    const int n0 = blockIdx.x * 128;
    const int t = blockIdx.y >> 1, b0 = (blockIdx.y & 1) * 128;
    const uint32_t sb = s2u(dsm);
    const uint32_t fmb = s2u(s_full), emb = s2u(s_empty);

    if (tid == 0)
        for (int s = 0; s < 4; s++) { MBINIT(fmb + s * 8, 1); MBINIT(emb + s * 8, 256); }
    __syncthreads();

    if (tid >= 256) {
        if (tid == 256) {
            for (int ck = 0; ck < 7; ck++) {
                const int s = ck & 3;
                if (ck >= 4) MBWAIT(emb + s * 8, ((ck >> 2) - 1) & 1);
                const uint32_t st = sb + (uint32_t)s * XG_STAGE;
                const uint32_t bar = fmb + s * 8;
                MBEXPECT(bar, 32768u);
                BULK(st,          &g_xpk[(((size_t)t * 7 + ck) * BB + b0) * 64], 16384u, bar);
                BULK(st + 16384u, &g_wipk[((size_t)ck * G4 + n0) * 64],          16384u, bar);
            }
        }
        return;
    }

    const int wy = wid >> 2, wx = wid & 3;
    float acc[4][4][4];
#pragma unroll
    for (int i = 0; i < 4; i++)
#pragma unroll
        for (int j = 0; j < 4; j++)
#pragma unroll
            for (int k = 0; k < 4; k++) acc[i][j][k] = 0.f;

#pragma unroll 1
    for (int ck = 0; ck < 7; ck++) {
        const int s = ck & 3;
        MBWAIT(fmb + s * 8, (ck >> 2) & 1);
        const uint32_t st = sb + (uint32_t)s * XG_STAGE;
        fused1_chunk<4>(st, st + 16384u, wy * 64, wx * 32, lane, acc);
        MBARRIVE(emb + s * 8);
    }

    BARC();
    float* sacc = (float*)dsm;
    store_acc<4>(sacc, XG_PITCH, acc, wy * 64, wx * 32, lane);
    BARC();
    for (int e = tid; e < 128 * 32; e += 256) {
        const int m = e >> 5, q = e & 31;
        float4 g = *(float4*)&sacc[m * XG_PITCH + q * 4];
        const float4 bs = *(const float4*)&g_bsum[n0 + q * 4];
        g.x += bs.x; g.y += bs.y; g.z += bs.z; g.w += bs.w;
        const int n = n0 + q * 4;
        const int nt = n >> 6, col = n & 63;
        *(float4*)&g_xg[(((size_t)t * 64 + nt) * 256 + (b0 + m)) * 64 + col] = g;
    }
}

// ---------------- persistent LSTM recurrence ----------------
// grid (64, 2) = 128 CTAs, 1/SM. smem: W [128KB] | A ring [3x16KB] | xg buf [32KB].
// c lives in registers; epilogue via shfl exchange; per-chunk counters replace grid barrier.
#define W_SMEM 131072u
#define A_SMEM (W_SMEM)
#define XGBUF_OFF (W_SMEM + 49152u)
__global__ __launch_bounds__(288, 1) void step_persist() {
    extern __shared__ __align__(128) char dsm[];
    __shared__ __align__(8) uint64_t s_full[3], s_empty[3], s_wbar, s_xgf, s_xge;
    const int tid = threadIdx.x;
    const int lane = tid & 31, wid = tid >> 5;
    const int m0 = blockIdx.y * 128, n0 = blockIdx.x * 64;
    const int ck0 = blockIdx.x >> 2;             // chunk this CTA's h-slice belongs to
    const uint32_t sb = s2u(dsm);
    const uint32_t amem = sb + A_SMEM;
    const uint32_t fmb = s2u(s_full), emb = s2u(s_empty);
    const uint32_t wbar = s2u(&s_wbar), xgf = s2u(&s_xgf), xge = s2u(&s_xge);
    const float* xgs = (const float*)(dsm + XGBUF_OFF);
    const int wy = wid >> 1, wx = wid & 1;       // warp grid 4(m) x 2(n)

    if (tid == 0) {
        for (int s = 0; s < 3; s++) { MBINIT(fmb + s * 8, 1); MBINIT(emb + s * 8, 256); }
        MBINIT(wbar, 1); MBINIT(xgf, 1); MBINIT(xge, 256);
    }
    __syncthreads();

    // load resident W tile once
    if (tid == 256) {
        MBEXPECT(wbar, 131072u);
        for (int ck = 0; ck < 16; ck++)
            BULK(sb + (uint32_t)ck * 8192u, &g_wpk[((size_t)ck * G4 + n0) * 64], 8192u, wbar);
    }

    if (tid >= 256) {
        if (tid == 256) {
            volatile int* ctr = g_ckctr;
            for (int t = 0; t < TT; t++) {
                const int rb = t & 1;
                // xg prefetch for this step
                if (t > 0) MBWAIT(xge, (t - 1) & 1);
                MBEXPECT(xgf, 32768u);
                BULK(sb + XGBUF_OFF,
                     &g_xg[(((size_t)t * 64 + (n0 >> 6)) * 256 + m0) * 64], 32768u, xgf);
                // h chunks, gated by ring emptiness + distributed progress counters
                for (int ck = 0; ck < 16; ck++) {
                    const int it = t * 16 + ck;
                    const int s = it % 3;
                    if (it >= 3) MBWAIT(emb + s * 8, ((it / 3) - 1) & 1);
                    if (t > 0) { const int tgt = 8 * t; while (ctr[ck] < tgt) { } }
                    MBEXPECT(fmb + s * 8, 16384u);
                    BULK(amem + (uint32_t)s * 16384u,
                         &g_hp[rb][((size_t)ck * 256 + m0) * 64], 16384u, fmb + s * 8);
                }
            }
        }
        return;
    }

    MBWAIT(wbar, 0);

    float c_reg[8];
#pragma unroll
    for (int f = 0; f < 8; f++) c_reg[f] = 0.f;

#pragma unroll 1
    for (int t = 0; t < TT; t++) {
        const int wb = (t & 1) ^ 1;
        float acc[2][4][4];
#pragma unroll
        for (int i = 0; i < 2; i++)
#pragma unroll
            for (int j = 0; j < 4; j++)
#pragma unroll
                for (int k = 0; k < 4; k++) acc[i][j][k] = 0.f;

#pragma unroll 1
        for (int ck = 0; ck < 16; ck++) {
            const int it = t * 16 + ck;
            const int s = it % 3;
            MBWAIT(fmb + s * 8, (it / 3) & 1);
            fused1_chunk<2>(amem + (uint32_t)s * 16384u, sb + (uint32_t)ck * 8192u,
                            wy * 32, wx * 32, lane, acc);
            MBARRIVE(emb + s * 8);
        }

        // epilogue: xg add from smem, shfl-exchange gates, cell update (c in regs)
        MBWAIT(xgf, t & 1);
#pragma unroll
        for (int tm = 0; tm < 2; tm++)
#pragma unroll
            for (int tn = 0; tn < 4; tn++) {
                const int r = wy * 32 + tm * 16 + (lane >> 2);
                const int cb = wx * 32 + tn * 8 + (lane & 3) * 2;
                const float2 xa = *(const float2*)&xgs[r * 64 + cb];
                const float2 xb = *(const float2*)&xgs[(r + 8) * 64 + cb];
                const float v0 = acc[tm][tn][0] + xa.x;
                const float v1 = acc[tm][tn][1] + xa.y;
                const float v2 = acc[tm][tn][2] + xb.x;
                const float v3 = acc[tm][tn][3] + xb.y;
                const float s0 = __shfl_xor_sync(0xffffffffu, v0, 1);
                const float s1 = __shfl_xor_sync(0xffffffffu, v1, 1);
                const float s2 = __shfl_xor_sync(0xffffffffu, v2, 1);
                const float s3 = __shfl_xor_sync(0xffffffffu, v3, 1);
                const bool even = (lane & 1) == 0;
                const float gi = even ? v0 : s2;
                const float gf = even ? v1 : s3;
                const float gg = even ? s0 : v2;
                const float go = even ? s1 : v3;
                const int myrow = r + (even ? 0 : 8);
                const float si = 1.f / (1.f + __expf(-gi));
                const float sf = 1.f / (1.f + __expf(-gf));
                const float tg = tanhf(gg);
                const float so = 1.f / (1.f + __expf(-go));
                const int f = tm * 4 + tn;
                const float c = sf * c_reg[f] + si * tg;
                c_reg[f] = c;
                const float h = so * tanhf(c);
                const int j = (n0 >> 2) + (cb >> 2);
                const int gm = m0 + myrow;
                const int ck = j >> 6, col = j & 63;
                const int unit = (col >> 3) ^ (gm & 7);
                g_hp[wb][((size_t)ck * 256 + gm) * 64 + unit * 8 + (col & 7)] = __float2half_rn(h);
                if (t == TT - 1) g_hf[(size_t)gm * HH + j] = h;
            }
        MBARRIVE(xge);
        __threadfence();
        BARC();
        if (tid == 0) atomicAdd(&g_ckctr[ck0], 1);
    }
}

// ---------------- MLP head ----------------
__global__ __launch_bounds__(256) void mlp_kernel(
    const float* __restrict__ W1, const float* __restrict__ b1,
    const float* __restrict__ W2, const float* __restrict__ b2,
    float* __restrict__ out) {
    __shared__ float hrow[HH];
    __shared__ float red[256];
    const int b = blockIdx.x;
    const int tid = threadIdx.x;

    const float* __restrict__ h = &g_hf[(size_t)b * HH];
    for (int k = tid; k < HH; k += 256) hrow[k] = h[k];
    __syncthreads();

    float sum = 0.f;
    for (int cc = tid; cc < NCELL; cc += 256) {
        const float* __restrict__ w = &W1[(size_t)cc * HH];
        float acc = b1[cc];
        for (int k = 0; k < HH; k += 4) {
            const float4 wv = *(const float4*)&w[k];
            acc += hrow[k] * wv.x + hrow[k + 1] * wv.y + hrow[k + 2] * wv.z + hrow[k + 3] * wv.w;
        }
        sum += fmaxf(acc, 0.f) * W2[cc];
    }
    red[tid] = sum;
    __syncthreads();
    for (int s = 128; s > 0; s >>= 1) {
        if (tid < s) red[tid] += red[tid + s];
        __syncthreads();
    }
    if (tid == 0) out[b] = red[0] + b2[0];
}

// ---------------- launch ----------------
extern "C" void kernel_launch(void* const* d_in, const int* in_sizes, int n_in,
                              void* d_out, int out_size) {
    const float* xt  = (const float*)d_in[0];
    const float* xa  = (const float*)d_in[1];
    const float* xv  = (const float*)d_in[2];
    const float* Wih = (const float*)d_in[3];
    const float* Whh = (const float*)d_in[4];
    const float* bih = (const float*)d_in[5];
    const float* bhh = (const float*)d_in[6];
    const float* W1  = (const float*)d_in[7];
    const float* b1  = (const float*)d_in[8];
    const float* W2  = (const float*)d_in[9];
    const float* b2  = (const float*)d_in[10];
    float* out = (float*)d_out;

    const int DSM_XG = 4 * 32768;                    // 128KB
    const int DSM_ST = 131072 + 49152 + 32768;       // 208KB: W + A ring + xg buf
    cudaFuncSetAttribute(xg_kernel, cudaFuncAttributeMaxDynamicSharedMemorySize, DSM_XG);
    cudaFuncSetAttribute(step_persist, cudaFuncAttributeMaxDynamicSharedMemorySize, DSM_ST);

    init_kernel<<<(BB * HH + 255) / 256, 256>>>();
    prep_w<<<(int)(((size_t)G4 * HH + 255) / 256), 256>>>(Whh);
    prep_wi<<<(int)(((size_t)G4 * XP + 255) / 256), 256>>>(Wih, bih, bhh);
    prep_x<<<(int)(((size_t)TT * BB * XP + 255) / 256), 256>>>(xt, xa, xv);
    xg_kernel<<<dim3(32, 512), 288, DSM_XG>>>();
    step_persist<<<dim3(64, 2), 288, DSM_ST>>>();
    mlp_kernel<<<BB, 256>>>(W1, b1, W2, b2, out);
}

// round 15
// speedup vs baseline: 1.5916x; 1.0489x over previous
#include <cuda_runtime.h>
#include <cuda_fp16.h>
#include <cstdint>

// EFLSTM, fp16 mma.sync, persistent recurrence with distributed per-chunk sync.
//   phase 1: xg = x @ Wih^T + bias  (parallel fp16 GEMM, fp16 out, packed [t][nt][m][64])
//   phase 2: ONE persistent kernel, 128 co-resident CTAs, t=0..255. W_hh resident in
//            smem (128KB); h streamed via 4-stage bulk ring with ROTATED chunk order;
//            xg prefetched per step (fp16); c in registers; per-chunk atomic counters.
//   phase 3: MLP head
// R15 fix: prep_small grid was 16 threads short -> g_ckctr never reset on graph
// replay -> producer raced ahead (non-deterministic). Grid is now 3073 blocks.

#define BB 256
#define TT 256
#define D_TXT 300
#define D_AUD 74
#define D_VIS 35
#define DD 409
#define HH 1024
#define G4 4096
#define XP 448
#define NCELL 512

// ---------------- device scratch ----------------
__device__ __half g_hp[2][16 * 256 * 64];            // h images [buf], fp16
__device__ float g_hf[BB * HH];
__device__ __half g_wpk[(size_t)16 * G4 * 64];       // Whh image
__device__ __half g_wipk[(size_t)7 * G4 * 64];       // Wih image
__device__ __half g_xpk[(size_t)TT * 7 * BB * 64];   // x image
__device__ float g_bsum[G4];
__device__ __half g_xg[(size_t)TT * 64 * 256 * 64];  // packed [t][nt][m][64], fp16
__device__ int g_ckctr[16];                          // per-chunk progress counters

// ---------------- helpers ----------------
__device__ __forceinline__ uint32_t s2u(const void* p) {
    uint32_t a;
    asm("{ .reg .u64 t; cvta.to.shared.u64 t, %1; cvt.u32.u64 %0, t; }" : "=r"(a) : "l"(p));
    return a;
}
#define MBINIT(a, c) asm volatile("mbarrier.init.shared.b64 [%0], %1;" ::"r"(a), "r"(c) : "memory")
#define MBARRIVE(a) asm volatile("mbarrier.arrive.shared.b64 _, [%0];" ::"r"(a) : "memory")
#define MBWAIT(a, ph) do {                                                                  \
    uint32_t _d;                                                                            \
    asm volatile("{\n .reg .pred p;\n mbarrier.try_wait.parity.acquire.cta.shared::cta.b64 p,[%1],%2;\n selp.b32 %0,1,0,p;\n}" \
                 : "=r"(_d) : "r"(a), "r"(ph) : "memory");                                  \
    while (!_d) {                                                                           \
        asm volatile("{\n .reg .pred p;\n mbarrier.try_wait.parity.acquire.cta.shared::cta.b64 p,[%1],%2,0x989680;\n selp.b32 %0,1,0,p;\n}" \
                     : "=r"(_d) : "r"(a), "r"(ph) : "memory");                              \
    }                                                                                       \
} while (0)
#define MBEXPECT(bar, bytes) \
    asm volatile("mbarrier.arrive.expect_tx.shared.b64 _, [%0], %1;" ::"r"(bar), "r"(bytes) : "memory")
#define BULK(dst, src, bytes, bar)                                                          \
    asm volatile("cp.async.bulk.shared::cluster.global.mbarrier::complete_tx::bytes "       \
                 "[%0], [%1], %2, [%3];"                                                    \
                 ::"r"(dst), "l"((const void*)(src)), "r"(bytes), "r"(bar) : "memory")
#define BARC() asm volatile("bar.sync 1, 256;" ::: "memory")
#define LDSM4(r, a)                                                                         \
    asm volatile("ldmatrix.sync.aligned.m8n8.x4.shared.b16 {%0,%1,%2,%3}, [%4];"            \
                 : "=r"((r)[0]), "=r"((r)[1]), "=r"((r)[2]), "=r"((r)[3]) : "r"(a))
#define MMAH(acc, a, b0, b1)                                                                \
    asm volatile("mma.sync.aligned.m16n8k16.row.col.f32.f16.f16.f32 "                       \
                 "{%0,%1,%2,%3}, {%4,%5,%6,%7}, {%8,%9}, {%0,%1,%2,%3};"                    \
                 : "+f"((acc)[0]), "+f"((acc)[1]), "+f"((acc)[2]), "+f"((acc)[3])           \
                 : "r"((a)[0]), "r"((a)[1]), "r"((a)[2]), "r"((a)[3]), "r"(b0), "r"(b1))

// single-term fp16 chunk over K=64. Warp tile (TM*16) x 32.
// smem tiles: row-major [rows][64 fp16], 128B/row, swizzle off ^ ((row&7)<<4).
template <int TM>
__device__ __forceinline__ void fused1_chunk(
    uint32_t sA, uint32_t sB, int mbase, int nbase, int lane, float acc[TM][4][4])
{
#pragma unroll
    for (int kk = 0; kk < 4; kk++) {
        uint32_t b[2][4];
#pragma unroll
        for (int tn = 0; tn < 2; tn++) {
            const uint32_t g = (uint32_t)(lane >> 3);
            const uint32_t row = (uint32_t)(nbase + tn * 16) + ((g >> 1) << 3) + (uint32_t)(lane & 7);
            const uint32_t kb = (uint32_t)(kk * 32) + ((g & 1u) << 4);
            const uint32_t off = row * 128u + (kb ^ ((row & 7u) << 4));
            LDSM4(b[tn], sB + off);
        }
#pragma unroll
        for (int tm = 0; tm < TM; tm++) {
            uint32_t a[4];
            const uint32_t row = (uint32_t)(mbase + tm * 16 + (lane & 15));
            const uint32_t kb = (uint32_t)(kk * 32) + ((uint32_t)(lane >> 4) << 4);
            const uint32_t off = row * 128u + (kb ^ ((row & 7u) << 4));
            LDSM4(a, sA + off);
#pragma unroll
            for (int tn = 0; tn < 4; tn++)
                MMAH(acc[tm][tn], a, b[tn >> 1][(tn & 1) * 2], b[tn >> 1][(tn & 1) * 2 + 1]);
        }
    }
}

template <int TM>
__device__ __forceinline__ void store_acc(float* sacc, int pitch, float acc[TM][4][4],
                                          int mbase, int nbase, int lane) {
#pragma unroll
    for (int tm = 0; tm < TM; tm++)
#pragma unroll
        for (int tn = 0; tn < 4; tn++) {
            const int r = mbase + tm * 16 + (lane >> 2);
            const int cc = nbase + tn * 8 + (lane & 3) * 2;
            *(float2*)&sacc[r * pitch + cc] = make_float2(acc[tm][tn][0], acc[tm][tn][1]);
            *(float2*)&sacc[(r + 8) * pitch + cc] = make_float2(acc[tm][tn][2], acc[tm][tn][3]);
        }
}

// ---------------- fused small prep: Whh image | Wih image+bias | h/ctr init ----------
// zone0: 524288 thr (prep_w, 8 halves each), zone1: 229376 (prep_wi),
// zone2: 32768 (h init) + 16 (ctr reset). TOTAL 786448 -> 3073 blocks of 256.
#define Z0 524288
#define Z1 229376
#define PREP_THREADS (Z0 + Z1 + 32768 + 16)
__global__ void prep_small(const float* __restrict__ Whh, const float* __restrict__ Wih,
                           const float* __restrict__ bih, const float* __restrict__ bhh) {
    const int i = blockIdx.x * 256 + threadIdx.x;
    if (i >= PREP_THREADS) return;
    if (i < Z0) {
        // (ck, n, unit) -> 8 contiguous k
        const int unit = i & 7, n = (i >> 3) & 4095, ck = i >> 15;
        const int gc = (n & 3) * HH + (n >> 2);
        const int kb = ck * 64 + ((unit ^ (n & 7)) << 3);
        const float4 w0 = *(const float4*)&Whh[(size_t)gc * HH + kb];
        const float4 w1 = *(const float4*)&Whh[(size_t)gc * HH + kb + 4];
        __half h8[8];
        h8[0] = __float2half_rn(w0.x); h8[1] = __float2half_rn(w0.y);
        h8[2] = __float2half_rn(w0.z); h8[3] = __float2half_rn(w0.w);
        h8[4] = __float2half_rn(w1.x); h8[5] = __float2half_rn(w1.y);
        h8[6] = __float2half_rn(w1.z); h8[7] = __float2half_rn(w1.w);
        *(uint4*)&g_wpk[(size_t)i * 8] = *(uint4*)h8;
    } else if (i < Z0 + Z1) {
        const int j = i - Z0;
        const int unit = j & 7, n = (j >> 3) & 4095, ck = j >> 15;
        const int gc = (n & 3) * HH + (n >> 2);
        const int kb = ck * 64 + ((unit ^ (n & 7)) << 3);
        __half h8[8];
#pragma unroll
        for (int u = 0; u < 8; u++) {
            const int k = kb + u;
            h8[u] = __float2half_rn(k < DD ? Wih[(size_t)gc * DD + k] : 0.f);
        }
        *(uint4*)&g_wipk[(size_t)j * 8] = *(uint4*)h8;
        if (ck == 0 && unit == 0) g_bsum[n] = bih[gc] + bhh[gc];
    } else {
        const int j = i - Z0 - Z1;
        if (j < 32768) {
            uint4 z = make_uint4(0u, 0u, 0u, 0u);
            *(uint4*)&g_hp[0][(size_t)j * 8] = z;
        } else {
            g_ckctr[j - 32768] = 0;   // j in [32768, 32784): reset progress counters
        }
    }
}

// ---------------- prep_x: x image, 8 halves per thread ----------------
__global__ void prep_x(const float* __restrict__ xt, const float* __restrict__ xa,
                       const float* __restrict__ xv) {
    const int i = blockIdx.x * 256 + threadIdx.x;
    if (i >= TT * 7 * BB * 8) return;
    const int unit = i & 7, b = (i >> 3) & 255;
    const int ck = (i >> 11) % 7, t = i / (7 * 2048);
    const int db = ck * 64 + ((unit ^ (b & 7)) << 3);
    __half h8[8];
#pragma unroll
    for (int u = 0; u < 8; u++) {
        const int d = db + u;
        float v = 0.f;
        if (d < D_TXT)              v = xt[((size_t)b * TT + t) * D_TXT + d];
        else if (d < D_TXT + D_AUD) v = xa[((size_t)b * TT + t) * D_AUD + (d - D_TXT)];
        else if (d < DD)            v = xv[((size_t)b * TT + t) * D_VIS + (d - D_TXT - D_AUD)];
        h8[u] = __float2half_rn(v);
    }
    *(uint4*)&g_xpk[(size_t)i * 8] = *(uint4*)h8;
}

// ---------------- xg GEMM: xg = x @ Wih^T + bias (fp16) -> packed fp16 ----------------
#define XG_PITCH 132
#define XG_STAGE 32768u
__global__ __launch_bounds__(288, 1) void xg_kernel() {
    extern __shared__ __align__(128) char dsm[];
    __shared__ __align__(8) uint64_t s_full[4], s_empty[4];
    const int tid = threadIdx.x;
    const int lane = tid & 31, wid = tid >> 5;
    const int n0 = blockIdx.x * 128;
    const int t = blockIdx.y >> 1, b0 = (blockIdx.y & 1) * 128;
    const uint32_t sb = s2u(dsm);
    const uint32_t fmb = s2u(s_full), emb = s2u(s_empty);

    if (tid == 0)
        for (int s = 0; s < 4; s++) { MBINIT(fmb + s * 8, 1); MBINIT(emb + s * 8, 256); }
    __syncthreads();

    if (tid >= 256) {
        if (tid == 256) {
            for (int ck = 0; ck < 7; ck++) {
                const int s = ck & 3;
                if (ck >= 4) MBWAIT(emb + s * 8, ((ck >> 2) - 1) & 1);
                const uint32_t st = sb + (uint32_t)s * XG_STAGE;
                const uint32_t bar = fmb + s * 8;
                MBEXPECT(bar, 32768u);
                BULK(st,          &g_xpk[(((size_t)t * 7 + ck) * BB + b0) * 64], 16384u, bar);
                BULK(st + 16384u, &g_wipk[((size_t)ck * G4 + n0) * 64],          16384u, bar);
            }
        }
        return;
    }

    const int wy = wid >> 2, wx = wid & 3;
    float acc[4][4][4];
#pragma unroll
    for (int i = 0; i < 4; i++)
#pragma unroll
        for (int j = 0; j < 4; j++)
#pragma unroll
            for (int k = 0; k < 4; k++) acc[i][j][k] = 0.f;

#pragma unroll 1
    for (int ck = 0; ck < 7; ck++) {
        const int s = ck & 3;
        MBWAIT(fmb + s * 8, (ck >> 2) & 1);
        const uint32_t st = sb + (uint32_t)s * XG_STAGE;
        fused1_chunk<4>(st, st + 16384u, wy * 64, wx * 32, lane, acc);
        MBARRIVE(emb + s * 8);
    }

    BARC();
    float* sacc = (float*)dsm;
    store_acc<4>(sacc, XG_PITCH, acc, wy * 64, wx * 32, lane);
    BARC();
    for (int e = tid; e < 128 * 32; e += 256) {
        const int m = e >> 5, q = e & 31;
        float4 g = *(float4*)&sacc[m * XG_PITCH + q * 4];
        const float4 bs = *(const float4*)&g_bsum[n0 + q * 4];
        const int n = n0 + q * 4;
        const int nt = n >> 6, col = n & 63;
        __half2* dst = (__half2*)&g_xg[(((size_t)t * 64 + nt) * 256 + (b0 + m)) * 64 + col];
        dst[0] = __floats2half2_rn(g.x + bs.x, g.y + bs.y);
        dst[1] = __floats2half2_rn(g.z + bs.z, g.w + bs.w);
    }
}

// ---------------- persistent LSTM recurrence ----------------
// grid (64, 2) = 128 CTAs, 1/SM. smem: W [128KB] | A ring [4x16KB] | xg buf fp16 [16KB].
// c in registers; rotated chunk order; per-chunk counters.
#define W_SMEM 131072u
#define XGBUF_OFF (W_SMEM + 65536u)
__global__ __launch_bounds__(288, 1) void step_persist() {
    extern __shared__ __align__(128) char dsm[];
    __shared__ __align__(8) uint64_t s_full[4], s_empty[4], s_wbar, s_xgf, s_xge;
    const int tid = threadIdx.x;
    const int lane = tid & 31, wid = tid >> 5;
    const int m0 = blockIdx.y * 128, n0 = blockIdx.x * 64;
    const int ck0 = blockIdx.x >> 2;             // chunk this CTA's h-slice belongs to
    const uint32_t sb = s2u(dsm);
    const uint32_t amem = sb + W_SMEM;
    const uint32_t fmb = s2u(s_full), emb = s2u(s_empty);
    const uint32_t wbar = s2u(&s_wbar), xgf = s2u(&s_xgf), xge = s2u(&s_xge);
    const __half* xgs = (const __half*)(dsm + XGBUF_OFF);
    const int wy = wid >> 1, wx = wid & 1;       // warp grid 4(m) x 2(n)

    if (tid == 0) {
        for (int s = 0; s < 4; s++) { MBINIT(fmb + s * 8, 1); MBINIT(emb + s * 8, 256); }
        MBINIT(wbar, 1); MBINIT(xgf, 1); MBINIT(xge, 256);
    }
    __syncthreads();

    // load resident W tile once
    if (tid == 256) {
        MBEXPECT(wbar, 131072u);
        for (int ck = 0; ck < 16; ck++)
            BULK(sb + (uint32_t)ck * 8192u, &g_wpk[((size_t)ck * G4 + n0) * 64], 8192u, wbar);
    }

    if (tid >= 256) {
        if (tid == 256) {
            volatile int* ctr = g_ckctr;
            for (int t = 0; t < TT; t++) {
                const int rb = t & 1;
                if (t > 0) MBWAIT(xge, (t - 1) & 1);
                MBEXPECT(xgf, 16384u);
                BULK(sb + XGBUF_OFF,
                     &g_xg[(((size_t)t * 64 + (n0 >> 6)) * 256 + m0) * 64], 16384u, xgf);
                for (int i = 0; i < 16; i++) {
                    const int ck = (ck0 + i) & 15;     // rotated chunk order
                    const int it = t * 16 + i;
                    const int s = it & 3;
                    if (it >= 4) MBWAIT(emb + s * 8, ((it >> 2) - 1) & 1);
                    if (t > 0) { const int tgt = 8 * t; while (ctr[ck] < tgt) { } }
                    MBEXPECT(fmb + s * 8, 16384u);
                    BULK(amem + (uint32_t)s * 16384u,
                         &g_hp[rb][((size_t)ck * 256 + m0) * 64], 16384u, fmb + s * 8);
                }
            }
        }
        return;
    }

    MBWAIT(wbar, 0);

    float c_reg[8];
#pragma unroll
    for (int f = 0; f < 8; f++) c_reg[f] = 0.f;

#pragma unroll 1
    for (int t = 0; t < TT; t++) {
        const int wb = (t & 1) ^ 1;
        float acc[2][4][4];
#pragma unroll
        for (int i = 0; i < 2; i++)
#pragma unroll
            for (int j = 0; j < 4; j++)
#pragma unroll
                for (int k = 0; k < 4; k++) acc[i][j][k] = 0.f;

#pragma unroll 1
        for (int i = 0; i < 16; i++) {
            const int ck = (ck0 + i) & 15;             // rotated chunk order
            const int it = t * 16 + i;
            const int s = it & 3;
            MBWAIT(fmb + s * 8, (it >> 2) & 1);
            fused1_chunk<2>(amem + (uint32_t)s * 16384u, sb + (uint32_t)ck * 8192u,
                            wy * 32, wx * 32, lane, acc);
            MBARRIVE(emb + s * 8);
        }

        // epilogue: xg add (fp16 smem), shfl-exchange gates, cell update (c in regs)
        MBWAIT(xgf, t & 1);
#pragma unroll
        for (int tm = 0; tm < 2; tm++)
#pragma unroll
            for (int tn = 0; tn < 4; tn++) {
                const int r = wy * 32 + tm * 16 + (lane >> 2);
                const int cb = wx * 32 + tn * 8 + (lane & 3) * 2;
                const float2 xa = __half22float2(*(const __half2*)&xgs[r * 64 + cb]);
                const float2 xb = __half22float2(*(const __half2*)&xgs[(r + 8) * 64 + cb]);
                const float v0 = acc[tm][tn][0] + xa.x;
                const float v1 = acc[tm][tn][1] + xa.y;
                const float v2 = acc[tm][tn][2] + xb.x;
                const float v3 = acc[tm][tn][3] + xb.y;
                const float s0 = __shfl_xor_sync(0xffffffffu, v0, 1);
                const float s1 = __shfl_xor_sync(0xffffffffu, v1, 1);
                const float s2 = __shfl_xor_sync(0xffffffffu, v2, 1);
                const float s3 = __shfl_xor_sync(0xffffffffu, v3, 1);
                const bool even = (lane & 1) == 0;
                const float gi = even ? v0 : s2;
                const float gf = even ? v1 : s3;
                const float gg = even ? s0 : v2;
                const float go = even ? s1 : v3;
                const int myrow = r + (even ? 0 : 8);
                const float si = 1.f / (1.f + __expf(-gi));
                const float sf = 1.f / (1.f + __expf(-gf));
                const float tg = tanhf(gg);
                const float so = 1.f / (1.f + __expf(-go));
                const int f = tm * 4 + tn;
                const float c = sf * c_reg[f] + si * tg;
                c_reg[f] = c;
                const float h = so * tanhf(c);
                const int j = (n0 >> 2) + (cb >> 2);
                const int gm = m0 + myrow;
                const int ck = j >> 6, col = j & 63;
                const int unit = (col >> 3) ^ (gm & 7);
                g_hp[wb][((size_t)ck * 256 + gm) * 64 + unit * 8 + (col & 7)] = __float2half_rn(h);
                if (t == TT - 1) g_hf[(size_t)gm * HH + j] = h;
            }
        MBARRIVE(xge);
        __threadfence();
        BARC();
        if (tid == 0) atomicAdd(&g_ckctr[ck0], 1);
    }
}

// ---------------- MLP head ----------------
__global__ __launch_bounds__(256) void mlp_kernel(
    const float* __restrict__ W1, const float* __restrict__ b1,
    const float* __restrict__ W2, const float* __restrict__ b2,
    float* __restrict__ out) {
    __shared__ float hrow[HH];
    __shared__ float red[256];
    const int b = blockIdx.x;
    const int tid = threadIdx.x;

    const float* __restrict__ h = &g_hf[(size_t)b * HH];
    for (int k = tid; k < HH; k += 256) hrow[k] = h[k];
    __syncthreads();

    float sum = 0.f;
    for (int cc = tid; cc < NCELL; cc += 256) {
        const float* __restrict__ w = &W1[(size_t)cc * HH];
        float acc = b1[cc];
        for (int k = 0; k < HH; k += 4) {
            const float4 wv = *(const float4*)&w[k];
            acc += hrow[k] * wv.x + hrow[k + 1] * wv.y + hrow[k + 2] * wv.z + hrow[k + 3] * wv.w;
        }
        sum += fmaxf(acc, 0.f) * W2[cc];
    }
    red[tid] = sum;
    __syncthreads();
    for (int s = 128; s > 0; s >>= 1) {
        if (tid < s) red[tid] += red[tid + s];
        __syncthreads();
    }
    if (tid == 0) out[b] = red[0] + b2[0];
}

// ---------------- launch ----------------
extern "C" void kernel_launch(void* const* d_in, const int* in_sizes, int n_in,
                              void* d_out, int out_size) {
    const float* xt  = (const float*)d_in[0];
    const float* xa  = (const float*)d_in[1];
    const float* xv  = (const float*)d_in[2];
    const float* Wih = (const float*)d_in[3];
    const float* Whh = (const float*)d_in[4];
    const float* bih = (const float*)d_in[5];
    const float* bhh = (const float*)d_in[6];
    const float* W1  = (const float*)d_in[7];
    const float* b1  = (const float*)d_in[8];
    const float* W2  = (const float*)d_in[9];
    const float* b2  = (const float*)d_in[10];
    float* out = (float*)d_out;

    const int DSM_XG = 4 * 32768;                    // 128KB
    const int DSM_ST = 131072 + 65536 + 16384;       // 208KB: W + A ring(4) + xg fp16
    cudaFuncSetAttribute(xg_kernel, cudaFuncAttributeMaxDynamicSharedMemorySize, DSM_XG);
    cudaFuncSetAttribute(step_persist, cudaFuncAttributeMaxDynamicSharedMemorySize, DSM_ST);

    prep_small<<<(PREP_THREADS + 255) / 256, 256>>>(Whh, Wih, bih, bhh);  // 3073 blocks
    prep_x<<<(TT * 7 * BB * 8 + 255) / 256, 256>>>(xt, xa, xv);
    xg_kernel<<<dim3(32, 512), 288, DSM_XG>>>();
    step_persist<<<dim3(64, 2), 288, DSM_ST>>>();
    mlp_kernel<<<BB, 256>>>(W1, b1, W2, b2, out);
}